// round 4
// baseline (speedup 1.0000x reference)
#include <cuda_runtime.h>

#define NN 50000
#define EE 800000
#define FIN 128
#define HH 64
#define HX 128   // 2H

#define MSG_EPS 1e-7f
#define SCAN_NBLK ((NN + 255) / 256)   // 196
#define SCAT_BLOCKS ((EE + 255) / 256) // 3125
#define ENC_BLOCKS ((NN + 255) / 256)  // 196

// ---------------- device scratch (no allocation allowed) ----------------
__device__ int   g_src[EE];
__device__ int   g_dst[EE];
__device__ int   g_srcSorted[EE];
__device__ int   g_cnt[NN];            // must be 0 at run start (zeroed at run end)
__device__ int   g_off[NN + 1];
__device__ int   g_cursor[NN];
__device__ volatile unsigned long long g_state[SCAN_NBLK];  // lookback state, 0 at run start
__device__ float g_xenc[NN * HH];
__device__ float g_tmp[NN * HH];   // agg + residual (gen_conv "out")
__device__ float g_x1[NN * HH];    // conv1 output

// ---------------- convert + count (with per-block inline dtype detect) ----
// If data is int64, every odd 32-bit word of the first 512 words is a
// high-word of a value < 2^31 -> zero. If int32, those are random node ids.
__global__ void convert_count_kernel(const int* __restrict__ ei32) {
    __shared__ int s_is64;
    int t = threadIdx.x;
    int v = ei32[2 * t + 1];
    int any = __syncthreads_or(v != 0);
    if (t == 0) s_is64 = !any;
    __syncthreads();
    int is64 = s_is64;

    int e = blockIdx.x * blockDim.x + t;
    if (e >= EE) return;
    int s, d;
    if (is64) {
        const long long* p = (const long long*)ei32;
        s = (int)p[e];
        d = (int)p[EE + e];
    } else {
        s = ei32[e];
        d = ei32[EE + e];
    }
    g_src[e] = s;
    g_dst[e] = d;
    atomicAdd(&g_cnt[d], 1);
}

// ---- block exclusive scan helper ----
__device__ __forceinline__ int block_excl_scan_256(int v, int* wsum, int t) {
    int lane = t & 31;
    int w = t >> 5;
    int incl = v;
#pragma unroll
    for (int o = 1; o < 32; o <<= 1) {
        int n = __shfl_up_sync(0xffffffffu, incl, o);
        if (lane >= o) incl += n;
    }
    if (lane == 31) wsum[w] = incl;
    __syncthreads();
    if (t == 0) {
        int run = 0;
#pragma unroll
        for (int i = 0; i < 8; i++) { int c = wsum[i]; wsum[i] = run; run += c; }
        wsum[8] = run;  // block total
    }
    __syncthreads();
    return incl - v + wsum[w];
}

// ---- single-pass decoupled-lookback scan: g_cnt -> g_off, g_cursor ----
// status in bits[32:34): 1 = aggregate, 2 = inclusive prefix. value in low 32.
__global__ void scan_lb_kernel() {
    __shared__ int wsum[9];
    __shared__ int s_excl;
    int b = blockIdx.x, t = threadIdx.x;
    int idx = b * 256 + t;
    int v = (idx < NN) ? g_cnt[idx] : 0;
    int excl = block_excl_scan_256(v, wsum, t);
    int total = wsum[8];

    if (t == 0) {
        unsigned long long st = (b == 0)
            ? ((2ULL << 32) | (unsigned)total)
            : ((1ULL << 32) | (unsigned)total);
        atomicExch((unsigned long long*)&g_state[b], st);
        if (b == 0) s_excl = 0;
    }
    if (b > 0 && t < 32) {
        int lane = t;
        int look = b - 1;
        int run = 0;
        while (true) {
            int ip = look - lane;
            unsigned long long s;
            if (ip >= 0) {
                do { s = g_state[ip]; } while ((s >> 32) == 0);
            } else {
                s = (2ULL << 32);  // virtual prefix 0
            }
            int isPref = ((s >> 32) == 2u);
            unsigned mask = __ballot_sync(0xffffffffu, isPref);
            int val = (int)(s & 0xffffffffu);
            if (mask) {
                int p = __ffs(mask) - 1;          // closest prefix
                int contrib = (lane <= p) ? val : 0;
#pragma unroll
                for (int o = 16; o; o >>= 1) contrib += __shfl_xor_sync(0xffffffffu, contrib, o);
                run += contrib;
                break;
            } else {
                int contrib = val;
#pragma unroll
                for (int o = 16; o; o >>= 1) contrib += __shfl_xor_sync(0xffffffffu, contrib, o);
                run += contrib;
                look -= 32;
            }
        }
        if (lane == 0) {
            s_excl = run;
            atomicExch((unsigned long long*)&g_state[b],
                       (2ULL << 32) | (unsigned)(run + total));
        }
    }
    __syncthreads();
    int base = s_excl;
    if (idx < NN) { int off = excl + base; g_off[idx] = off; g_cursor[idx] = off; }
    if (b == SCAN_NBLK - 1 && t == 0) g_off[NN] = EE;
}

// ---------------- fused scatter + encoder ----------------
// blocks [0, SCAT_BLOCKS): scatter edges into CSR order
// blocks [SCAT_BLOCKS, +ENC_BLOCKS): encoder GEMM x[N,128] @ W[128,64] + b
__global__ void __launch_bounds__(256) scatter_enc_kernel(
    const float* __restrict__ x, const float* __restrict__ W,
    const float* __restrict__ b) {
    __shared__ float Ws[FIN * HH];  // 32 KB (allocated for all blocks)
    if (blockIdx.x < SCAT_BLOCKS) {
        int e = blockIdx.x * 256 + threadIdx.x;
        if (e < EE) {
            int d = g_dst[e];
            int pos = atomicAdd(&g_cursor[d], 1);
            g_srcSorted[pos] = g_src[e];
        }
        return;
    }
    for (int i = threadIdx.x; i < FIN * HH; i += blockDim.x) Ws[i] = W[i];
    __syncthreads();
    int row = (blockIdx.x - SCAT_BLOCKS) * 256 + threadIdx.x;
    if (row >= NN) return;

    float4 acc[16];
#pragma unroll
    for (int i = 0; i < 16; i++) acc[i] = make_float4(0.f, 0.f, 0.f, 0.f);

    const float4* xr = (const float4*)(x + (size_t)row * FIN);
    const float4* W4 = (const float4*)Ws;
#pragma unroll 4
    for (int k4 = 0; k4 < FIN / 4; k4++) {
        float4 a = xr[k4];
        float av[4] = {a.x, a.y, a.z, a.w};
#pragma unroll
        for (int kk = 0; kk < 4; kk++) {
            int k = k4 * 4 + kk;
            float aval = av[kk];
#pragma unroll
            for (int c = 0; c < 16; c++) {
                float4 w = W4[k * 16 + c];
                acc[c].x += aval * w.x;
                acc[c].y += aval * w.y;
                acc[c].z += aval * w.z;
                acc[c].w += aval * w.w;
            }
        }
    }
    const float4* b4 = (const float4*)b;
    float4* outp = (float4*)(g_xenc + (size_t)row * HH);
#pragma unroll
    for (int c = 0; c < 16; c++) {
        float4 bb = b4[c];
        outp[c] = make_float4(acc[c].x + bb.x, acc[c].y + bb.y,
                              acc[c].z + bb.z, acc[c].w + bb.w);
    }
}

// ---------------- softmax aggregation: warp per dst node ----------------
__global__ void agg_kernel(int sel, const float* __restrict__ tptr) {
    const float* __restrict__ xin = sel ? g_x1 : g_xenc;
    int gw = (blockIdx.x * blockDim.x + threadIdx.x) >> 5;
    int lane = threadIdx.x & 31;
    if (gw >= NN) return;
    float t = *tptr;
    int e0 = g_off[gw], e1 = g_off[gw + 1];

    float S0 = 0.f, S1 = 0.f, A0 = 0.f, A1 = 0.f;

    int e = e0;
    for (; e + 4 <= e1; e += 4) {
        int s0 = g_srcSorted[e];
        int s1 = g_srcSorted[e + 1];
        int s2 = g_srcSorted[e + 2];
        int s3 = g_srcSorted[e + 3];
        float a0 = xin[(size_t)s0 * HH + lane];
        float b0 = xin[(size_t)s0 * HH + 32 + lane];
        float a1 = xin[(size_t)s1 * HH + lane];
        float b1 = xin[(size_t)s1 * HH + 32 + lane];
        float a2 = xin[(size_t)s2 * HH + lane];
        float b2 = xin[(size_t)s2 * HH + 32 + lane];
        float a3 = xin[(size_t)s3 * HH + lane];
        float b3 = xin[(size_t)s3 * HH + 32 + lane];

        float m, ex;
        m = fmaxf(a0, 0.f) + MSG_EPS; ex = __expf(m * t); S0 += ex; A0 += m * ex;
        m = fmaxf(b0, 0.f) + MSG_EPS; ex = __expf(m * t); S1 += ex; A1 += m * ex;
        m = fmaxf(a1, 0.f) + MSG_EPS; ex = __expf(m * t); S0 += ex; A0 += m * ex;
        m = fmaxf(b1, 0.f) + MSG_EPS; ex = __expf(m * t); S1 += ex; A1 += m * ex;
        m = fmaxf(a2, 0.f) + MSG_EPS; ex = __expf(m * t); S0 += ex; A0 += m * ex;
        m = fmaxf(b2, 0.f) + MSG_EPS; ex = __expf(m * t); S1 += ex; A1 += m * ex;
        m = fmaxf(a3, 0.f) + MSG_EPS; ex = __expf(m * t); S0 += ex; A0 += m * ex;
        m = fmaxf(b3, 0.f) + MSG_EPS; ex = __expf(m * t); S1 += ex; A1 += m * ex;
    }
    for (; e < e1; e++) {
        int s = g_srcSorted[e];
        float a = xin[(size_t)s * HH + lane];
        float b = xin[(size_t)s * HH + 32 + lane];
        float m, ex;
        m = fmaxf(a, 0.f) + MSG_EPS; ex = __expf(m * t); S0 += ex; A0 += m * ex;
        m = fmaxf(b, 0.f) + MSG_EPS; ex = __expf(m * t); S1 += ex; A1 += m * ex;
    }
    float r0 = A0 / (S0 + 1e-16f);
    float r1 = A1 / (S1 + 1e-16f);
    g_tmp[(size_t)gw * HH + lane]      = r0 + xin[(size_t)gw * HH + lane];
    g_tmp[(size_t)gw * HH + 32 + lane] = r1 + xin[(size_t)gw * HH + 32 + lane];
}

// ---------------- fused MLP (conv1): relu(LN(row@W1+b1)) @ W2 + b2 -> g_x1 --
__global__ void __launch_bounds__(128) mlp1_kernel(
    const float* __restrict__ W1, const float* __restrict__ b1,
    const float* __restrict__ g1, const float* __restrict__ be1,
    const float* __restrict__ W2, const float* __restrict__ b2) {
    __shared__ float rowS[2 * HH];
    __shared__ float hS[2][HX];
    __shared__ float part[2][HX];
    __shared__ float sred[2][4], qred[2][4];

    int tid = threadIdx.x;
    int lane = tid & 31;
    int w = tid >> 5;
    int oc = tid & 63;
    int half = tid >> 6;

    float w1c[HH];
#pragma unroll
    for (int k = 0; k < HH; k++) w1c[k] = W1[k * HX + tid];
    float b1v = b1[tid], g1v = g1[tid], be1v = be1[tid];
    float w2c[64];
#pragma unroll
    for (int k = 0; k < 64; k++) w2c[k] = W2[(half * 64 + k) * HH + oc];
    float b2v = b2[oc];

    const int NPAIR = NN / 2;
    for (int p = blockIdx.x; p < NPAIR; p += gridDim.x) {
        int r0 = 2 * p;
        __syncthreads();
        rowS[tid] = g_tmp[(size_t)r0 * HH + tid];
        __syncthreads();

        float h0 = b1v, h1 = b1v;
#pragma unroll
        for (int k = 0; k < HH; k++) {
            h0 += rowS[k] * w1c[k];
            h1 += rowS[HH + k] * w1c[k];
        }
        float s0 = h0, q0 = h0 * h0, s1 = h1, q1 = h1 * h1;
#pragma unroll
        for (int o = 16; o; o >>= 1) {
            s0 += __shfl_xor_sync(0xffffffffu, s0, o);
            q0 += __shfl_xor_sync(0xffffffffu, q0, o);
            s1 += __shfl_xor_sync(0xffffffffu, s1, o);
            q1 += __shfl_xor_sync(0xffffffffu, q1, o);
        }
        if (lane == 0) { sred[0][w] = s0; qred[0][w] = q0; sred[1][w] = s1; qred[1][w] = q1; }
        __syncthreads();
        float S0 = sred[0][0] + sred[0][1] + sred[0][2] + sred[0][3];
        float Q0 = qred[0][0] + qred[0][1] + qred[0][2] + qred[0][3];
        float S1 = sred[1][0] + sred[1][1] + sred[1][2] + sred[1][3];
        float Q1 = qred[1][0] + qred[1][1] + qred[1][2] + qred[1][3];
        float mu0 = S0 * (1.f / HX);
        float mu1 = S1 * (1.f / HX);
        float rs0 = rsqrtf(Q0 * (1.f / HX) - mu0 * mu0 + 1e-5f);
        float rs1 = rsqrtf(Q1 * (1.f / HX) - mu1 * mu1 + 1e-5f);
        hS[0][tid] = fmaxf((h0 - mu0) * rs0 * g1v + be1v, 0.f);
        hS[1][tid] = fmaxf((h1 - mu1) * rs1 * g1v + be1v, 0.f);
        __syncthreads();

        float acc0 = 0.f, acc1 = 0.f;
#pragma unroll
        for (int k = 0; k < 64; k++) {
            acc0 += hS[0][half * 64 + k] * w2c[k];
            acc1 += hS[1][half * 64 + k] * w2c[k];
        }
        part[0][tid] = acc0;
        part[1][tid] = acc1;
        __syncthreads();
        float v = part[half][oc] + part[half][oc + 64] + b2v;
        g_x1[(size_t)(r0 + half) * HH + oc] = v;
    }
}

// ------- conv2 MLP fused with the whole network epilogue -> d_out ---------
// h2 never hits global memory. Also re-zeroes g_cnt / g_state for next run.
__global__ void __launch_bounds__(128) mlp2_final_kernel(
    const float* __restrict__ W1, const float* __restrict__ b1,
    const float* __restrict__ g1, const float* __restrict__ be1,
    const float* __restrict__ W2, const float* __restrict__ b2,
    const float* __restrict__ ln1g, const float* __restrict__ ln1b,
    const float* __restrict__ ng, const float* __restrict__ nb,
    const float* __restrict__ lw, const float* __restrict__ lb,
    float* __restrict__ out) {
    __shared__ float rowS[2 * HH];
    __shared__ float hS[2][HX];
    __shared__ float part[2][HX];
    __shared__ float sred[2][4], qred[2][4];
    __shared__ float f1s[2][2], f1q[2][2];
    __shared__ float f2s[2][2], f2q[2][2];
    __shared__ float fd[2][2];

    int tid = threadIdx.x;
    int lane = tid & 31;
    int w = tid >> 5;
    int oc = tid & 63;
    int half = tid >> 6;
    int wh = w & 1;       // warp index within half

    float w1c[HH];
#pragma unroll
    for (int k = 0; k < HH; k++) w1c[k] = W1[k * HX + tid];
    float b1v = b1[tid], g1v = g1[tid], be1v = be1[tid];
    float w2c[64];
#pragma unroll
    for (int k = 0; k < 64; k++) w2c[k] = W2[(half * 64 + k) * HH + oc];
    float b2v = b2[oc];
    float l1g = ln1g[oc], l1b = ln1b[oc];
    float ngx = ng[oc], nbx = nb[oc];
    float ngh = ng[64 + oc], nbh = nb[64 + oc];
    float lwx = lw[oc], lwh = lw[64 + oc];
    float lbv = lb[0];

    const int NPAIR = NN / 2;
    for (int p = blockIdx.x; p < NPAIR; p += gridDim.x) {
        int r0 = 2 * p;
        __syncthreads();
        rowS[tid] = g_tmp[(size_t)r0 * HH + tid];
        __syncthreads();

        float h0 = b1v, h1 = b1v;
#pragma unroll
        for (int k = 0; k < HH; k++) {
            h0 += rowS[k] * w1c[k];
            h1 += rowS[HH + k] * w1c[k];
        }
        float s0 = h0, q0 = h0 * h0, s1 = h1, q1 = h1 * h1;
#pragma unroll
        for (int o = 16; o; o >>= 1) {
            s0 += __shfl_xor_sync(0xffffffffu, s0, o);
            q0 += __shfl_xor_sync(0xffffffffu, q0, o);
            s1 += __shfl_xor_sync(0xffffffffu, s1, o);
            q1 += __shfl_xor_sync(0xffffffffu, q1, o);
        }
        if (lane == 0) { sred[0][w] = s0; qred[0][w] = q0; sred[1][w] = s1; qred[1][w] = q1; }
        __syncthreads();
        float S0 = sred[0][0] + sred[0][1] + sred[0][2] + sred[0][3];
        float Q0 = qred[0][0] + qred[0][1] + qred[0][2] + qred[0][3];
        float S1 = sred[1][0] + sred[1][1] + sred[1][2] + sred[1][3];
        float Q1 = qred[1][0] + qred[1][1] + qred[1][2] + qred[1][3];
        float mu0 = S0 * (1.f / HX);
        float mu1 = S1 * (1.f / HX);
        float rs0 = rsqrtf(Q0 * (1.f / HX) - mu0 * mu0 + 1e-5f);
        float rs1 = rsqrtf(Q1 * (1.f / HX) - mu1 * mu1 + 1e-5f);
        hS[0][tid] = fmaxf((h0 - mu0) * rs0 * g1v + be1v, 0.f);
        hS[1][tid] = fmaxf((h1 - mu1) * rs1 * g1v + be1v, 0.f);
        __syncthreads();

        float acc0 = 0.f, acc1 = 0.f;
#pragma unroll
        for (int k = 0; k < 64; k++) {
            acc0 += hS[0][half * 64 + k] * w2c[k];
            acc1 += hS[1][half * 64 + k] * w2c[k];
        }
        part[0][tid] = acc0;
        part[1][tid] = acc1;
        __syncthreads();

        // --- this thread now owns h2 value of (row = r0+half, channel oc) ---
        float hv = part[half][oc] + part[half][oc + 64] + b2v;
        float xv = g_x1[(size_t)r0 * HH + tid];  // == g_x1[(r0+half)*64 + oc]

        // LN over 64 h-channels (per row), then relu
        float s = hv, q = hv * hv;
#pragma unroll
        for (int o = 16; o; o >>= 1) {
            s += __shfl_xor_sync(0xffffffffu, s, o);
            q += __shfl_xor_sync(0xffffffffu, q, o);
        }
        if (lane == 0) { f1s[half][wh] = s; f1q[half][wh] = q; }
        __syncthreads();
        float Sh = f1s[half][0] + f1s[half][1];
        float Qh = f1q[half][0] + f1q[half][1];
        float muh = Sh * (1.f / 64.f);
        float rsh = rsqrtf(Qh * (1.f / 64.f) - muh * muh + 1e-5f);
        float hn = fmaxf((hv - muh) * rsh * l1g + l1b, 0.f);

        // LN over concat [x1(64), hn(64)] = 128 channels, relu, dot lin_W
        float s2 = xv + hn;
        float q2 = xv * xv + hn * hn;
#pragma unroll
        for (int o = 16; o; o >>= 1) {
            s2 += __shfl_xor_sync(0xffffffffu, s2, o);
            q2 += __shfl_xor_sync(0xffffffffu, q2, o);
        }
        if (lane == 0) { f2s[half][wh] = s2; f2q[half][wh] = q2; }
        __syncthreads();
        float S2 = f2s[half][0] + f2s[half][1];
        float Q2 = f2q[half][0] + f2q[half][1];
        float mu2 = S2 * (1.f / 128.f);
        float rs2 = rsqrtf(Q2 * (1.f / 128.f) - mu2 * mu2 + 1e-5f);
        float yx = fmaxf((xv - mu2) * rs2 * ngx + nbx, 0.f);
        float yh = fmaxf((hn - mu2) * rs2 * ngh + nbh, 0.f);
        float d = yx * lwx + yh * lwh;
#pragma unroll
        for (int o = 16; o; o >>= 1) d += __shfl_xor_sync(0xffffffffu, d, o);
        if (lane == 0) fd[half][wh] = d;
        __syncthreads();
        if (oc == 0) out[r0 + half] = fd[half][0] + fd[half][1] + lbv;
    }

    // re-zero counters / lookback state for the next run
    for (int i = blockIdx.x * blockDim.x + tid; i < NN; i += gridDim.x * blockDim.x)
        g_cnt[i] = 0;
    {
        int i = blockIdx.x * blockDim.x + tid;
        if (i < SCAN_NBLK) *((unsigned long long*)&g_state[i]) = 0ULL;
    }
}

// ---------------- launch ----------------
extern "C" void kernel_launch(void* const* d_in, const int* in_sizes, int n_in,
                              void* d_out, int out_size) {
    const float* x    = (const float*)d_in[0];
    const void*  ei   = d_in[1];
    const float* encW = (const float*)d_in[2];
    const float* encB = (const float*)d_in[3];
    const float* t    = (const float*)d_in[4];
    const float* W1   = (const float*)d_in[5];
    const float* b1   = (const float*)d_in[6];
    const float* g1   = (const float*)d_in[7];
    const float* be1  = (const float*)d_in[8];
    const float* W2   = (const float*)d_in[9];
    const float* b2   = (const float*)d_in[10];
    const float* ln1g = (const float*)d_in[11];
    const float* ln1b = (const float*)d_in[12];
    const float* ng   = (const float*)d_in[13];
    const float* nb   = (const float*)d_in[14];
    const float* lw   = (const float*)d_in[15];
    const float* lb   = (const float*)d_in[16];
    float* out = (float*)d_out;

    const int AGG_BLOCKS = (NN * 32 + 255) / 256;
    const int MLP_BLOCKS = 444;   // 3 blocks/SM, one wave

    convert_count_kernel<<<SCAT_BLOCKS, 256>>>((const int*)ei);
    scan_lb_kernel<<<SCAN_NBLK, 256>>>();
    scatter_enc_kernel<<<SCAT_BLOCKS + ENC_BLOCKS, 256>>>(x, encW, encB);
    agg_kernel<<<AGG_BLOCKS, 256>>>(0, t);                       // launch #4 (ncu)
    mlp1_kernel<<<MLP_BLOCKS, 128>>>(W1, b1, g1, be1, W2, b2);
    agg_kernel<<<AGG_BLOCKS, 256>>>(1, t);
    mlp2_final_kernel<<<MLP_BLOCKS, 128>>>(W1, b1, g1, be1, W2, b2,
                                           ln1g, ln1b, ng, nb, lw, lb, out);
}